// round 9
// baseline (speedup 1.0000x reference)
#include <cuda_runtime.h>
#include <cstdint>

// Problem shape (fixed by reference)
#define BB 4
#define HH 16
#define SS 2048
#define DD 64
#define TQ 16            // queries per CTA
#define KC 64            // keys per fused chunk
#define NCHUNK (SS/KC)   // 32
#define NT 256
#define SCALE 0.125f

// conflict-free smem strides (stride mod 32 makes frag lane->bank bijective)
#define KSTR 72          // K planes [d][k]   : 72%32==8 -> bank 8*tg+g
#define VSTR 68          // V planes [d][k]   : 68%32==4 -> bank 4*g+tg
#define EC   68          // e chunk  [row][k] : 68%32==4 -> bank 4*g+tg
#define QLS  68          // Q-lo     [row][d] : 68%32==4
#define KPLANE (DD*KSTR) // 4608 floats
#define VPLANE (DD*VSTR) // 4352 floats

#define OUT_ELEMS (BB*HH*SS*DD)
#define NBH (BB*HH)

// smem floats: KH,KL + VH,VL + echunk + Qs + Qlo + part + invs
#define SMEM_FLOATS (2*KPLANE + 2*VPLANE + TQ*EC + TQ*DD + TQ*QLS + 128 + 16)
#define SMEM_BYTES  (SMEM_FLOATS * 4)

// per-row 1/sum scratch for the normalize kernel (no allocs allowed)
__device__ float g_inv[(size_t)NBH * SS];

__device__ __forceinline__ float tf32r(float x) {
    uint32_t u;
    asm("cvt.rna.tf32.f32 %0, %1;" : "=r"(u) : "f"(x));
    return __uint_as_float(u);
}

// D += A(16x8, tf32) * B(8x8, tf32), fp32 accumulate
#define MMA8(d, a0, a1, a2, a3, b0, b1)                                        \
    asm volatile(                                                              \
        "mma.sync.aligned.m16n8k8.row.col.f32.tf32.tf32.f32 "                  \
        "{%0,%1,%2,%3}, {%4,%5,%6,%7}, {%8,%9}, {%0,%1,%2,%3};"                \
        : "+f"(d[0]), "+f"(d[1]), "+f"(d[2]), "+f"(d[3])                       \
        : "r"(__float_as_uint(a0)), "r"(__float_as_uint(a1)),                  \
          "r"(__float_as_uint(a2)), "r"(__float_as_uint(a3)),                  \
          "r"(__float_as_uint(b0)), "r"(__float_as_uint(b1)))

__global__ __launch_bounds__(NT, 2)
void sdpa_fused(const float* __restrict__ Q, const float* __restrict__ K,
                const float* __restrict__ V, const int* __restrict__ mask,
                float* __restrict__ out, float* __restrict__ wts) {
    extern __shared__ float smem[];
    float* KH     = smem;                    // KPLANE
    float* KL     = KH + KPLANE;             // KPLANE
    float* VH     = KL + KPLANE;             // VPLANE
    float* VL     = VH + VPLANE;             // VPLANE
    float* echunk = VL + VPLANE;             // TQ * EC (unnormalized e, this chunk)
    float* Qs     = echunk + TQ * EC;        // TQ * DD (raw Q tile)
    float* Qlo    = Qs + TQ * DD;            // TQ * QLS (tf32-lo of Q*SCALE)
    float* part   = Qlo + TQ * QLS;          // [16][8]
    float* invs   = part + 128;              // [16]

    const int h  = blockIdx.x;
    const int q0 = blockIdx.y * TQ;
    const int b  = blockIdx.z;

    const int tid = threadIdx.x;
    const int w   = tid >> 5;     // warp 0..7
    const int l   = tid & 31;
    const int g   = l >> 2;       // 0..7
    const int tg  = l & 3;        // 0..3

    const size_t bh = (size_t)(b * HH + h);
    const float4* Q4 = (const float4*)(Q + bh * SS * DD + (size_t)q0 * DD);
    const float4* K4 = (const float4*)(K + bh * SS * DD);
    const float4* V4 = (const float4*)(V + bh * SS * DD);
    const int*    Mb = mask + (size_t)b * SS * SS + (size_t)q0 * SS;
    float* Ob = out + bh * SS * DD + (size_t)q0 * DD;
    float* Wb = wts + bh * SS * SS + (size_t)q0 * SS;

    // Q tile to smem (256 float4 == 1024 floats)
    ((float4*)Qs)[tid] = Q4[tid];

    // Prefetch K chunk 0 and V chunk 0 into registers.
    // thread owns d-cols {4w..4w+3, 4w+32..+35}, keys 32i+l (i<2)
    float4 preK[4], preV[4];
#pragma unroll
    for (int p = 0; p < 2; p++)
#pragma unroll
        for (int i = 0; i < 2; i++) {
            preK[p * 2 + i] = K4[(size_t)(32 * i + l) * (DD / 4) + w + 8 * p];
            preV[p * 2 + i] = V4[(size_t)(32 * i + l) * (DD / 4) + w + 8 * p];
        }
    __syncthreads();

    // Q hi fragments in regs (SCALE folded); Q lo plane in smem.
    float qh[8][4];
#pragma unroll
    for (int dk = 0; dk < 8; dk++) {
        qh[dk][0] = tf32r(Qs[g * DD + 8 * dk + tg] * SCALE);
        qh[dk][1] = tf32r(Qs[(g + 8) * DD + 8 * dk + tg] * SCALE);
        qh[dk][2] = tf32r(Qs[g * DD + 8 * dk + tg + 4] * SCALE);
        qh[dk][3] = tf32r(Qs[(g + 8) * DD + 8 * dk + tg + 4] * SCALE);
    }
    for (int i = tid; i < TQ * DD; i += NT) {
        const int r = i >> 6, cidx = i & 63;
        float q = Qs[i] * SCALE;
        Qlo[r * QLS + cidx] = tf32r(q - tf32r(q));
    }

    float s0 = 0.f, s1 = 0.f;          // row sums (rows g, g+8)
    float oacc[4] = {0.f, 0.f, 0.f, 0.f};

    for (int c = 0; c < NCHUNK; c++) {
        const int cbase = c * KC;
        __syncthreads();   // K/V planes + echunk free of previous readers

        // ---- stage K(c) hi/lo transposed ----
#pragma unroll
        for (int p = 0; p < 2; p++) {
            const int d0 = 4 * w + 32 * p;
#pragma unroll
            for (int i = 0; i < 2; i++) {
                const int k = 32 * i + l;
                float4 v = preK[p * 2 + i];
                float x, hi;
                x = v.x; hi = tf32r(x); KH[(d0 + 0) * KSTR + k] = hi; KL[(d0 + 0) * KSTR + k] = tf32r(x - hi);
                x = v.y; hi = tf32r(x); KH[(d0 + 1) * KSTR + k] = hi; KL[(d0 + 1) * KSTR + k] = tf32r(x - hi);
                x = v.z; hi = tf32r(x); KH[(d0 + 2) * KSTR + k] = hi; KL[(d0 + 2) * KSTR + k] = tf32r(x - hi);
                x = v.w; hi = tf32r(x); KH[(d0 + 3) * KSTR + k] = hi; KL[(d0 + 3) * KSTR + k] = tf32r(x - hi);
            }
        }
        __syncthreads();

        // prefetch K(c+1)
        if (c + 1 < NCHUNK) {
#pragma unroll
            for (int p = 0; p < 2; p++)
#pragma unroll
                for (int i = 0; i < 2; i++)
                    preK[p * 2 + i] =
                        K4[(size_t)((c + 1) * KC + 32 * i + l) * (DD / 4) + w + 8 * p];
        }
        // mask for this warp's n-tile (in flight during MMAs)
        const int colj = cbase + 8 * w + 2 * tg;
        int2 m0 = *(const int2*)&Mb[(size_t)g * SS + colj];
        int2 m1 = *(const int2*)&Mb[(size_t)(g + 8) * SS + colj];

        // ---- QK^T MMAs: warp w owns 8 keys (n-tile w), 16 rows, 3xTF32 ----
        float acc[4] = {0.f, 0.f, 0.f, 0.f};
#pragma unroll
        for (int dk = 0; dk < 8; dk++) {
            const float* ph = &KH[(8 * dk + tg) * KSTR + 8 * w + g];
            const float* pl = &KL[(8 * dk + tg) * KSTR + 8 * w + g];
            float bh0 = ph[0], bh1 = ph[4 * KSTR];
            float bl0 = pl[0], bl1 = pl[4 * KSTR];
            MMA8(acc, qh[dk][0], qh[dk][1], qh[dk][2], qh[dk][3], bh0, bh1);
            MMA8(acc, qh[dk][0], qh[dk][1], qh[dk][2], qh[dk][3], bl0, bl1);
            float l0 = Qlo[g * QLS + 8 * dk + tg];
            float l1 = Qlo[(g + 8) * QLS + 8 * dk + tg];
            float l2 = Qlo[g * QLS + 8 * dk + tg + 4];
            float l3 = Qlo[(g + 8) * QLS + 8 * dk + tg + 4];
            MMA8(acc, l0, l1, l2, l3, bh0, bh1);
        }

        // ---- epilogue: mask -> exp -> e to smem, row sums in regs ----
        {
            float e0 = m0.x ? __expf(acc[0]) : 0.f;
            float e1 = m0.y ? __expf(acc[1]) : 0.f;
            float e2 = m1.x ? __expf(acc[2]) : 0.f;
            float e3 = m1.y ? __expf(acc[3]) : 0.f;
            *(float2*)&echunk[g * EC + 8 * w + 2 * tg]       = make_float2(e0, e1);
            *(float2*)&echunk[(g + 8) * EC + 8 * w + 2 * tg] = make_float2(e2, e3);
            s0 += e0 + e1;
            s1 += e2 + e3;
        }

        // ---- stage V(c) hi/lo transposed (buffer free since top sync) ----
#pragma unroll
        for (int p = 0; p < 2; p++) {
            const int d0 = 4 * w + 32 * p;
#pragma unroll
            for (int i = 0; i < 2; i++) {
                const int k = 32 * i + l;
                float4 v = preV[p * 2 + i];
                float x, hi;
                x = v.x; hi = tf32r(x); VH[(d0 + 0) * VSTR + k] = hi; VL[(d0 + 0) * VSTR + k] = tf32r(x - hi);
                x = v.y; hi = tf32r(x); VH[(d0 + 1) * VSTR + k] = hi; VL[(d0 + 1) * VSTR + k] = tf32r(x - hi);
                x = v.z; hi = tf32r(x); VH[(d0 + 2) * VSTR + k] = hi; VL[(d0 + 2) * VSTR + k] = tf32r(x - hi);
                x = v.w; hi = tf32r(x); VH[(d0 + 3) * VSTR + k] = hi; VL[(d0 + 3) * VSTR + k] = tf32r(x - hi);
            }
        }
        // prefetch V(c+1)
        if (c + 1 < NCHUNK) {
#pragma unroll
            for (int p = 0; p < 2; p++)
#pragma unroll
                for (int i = 0; i < 2; i++)
                    preV[p * 2 + i] =
                        V4[(size_t)((c + 1) * KC + 32 * i + l) * (DD / 4) + w + 8 * p];
        }
        __syncthreads();   // echunk + V planes visible

        // ---- stream unnormalized weights: warp w owns rows 2w, 2w+1 ----
        {
            float2 a = *(const float2*)&echunk[(2 * w) * EC + 2 * l];
            float2 bv = *(const float2*)&echunk[(2 * w + 1) * EC + 2 * l];
            *(float2*)&Wb[(size_t)(2 * w) * SS + cbase + 2 * l]     = a;
            *(float2*)&Wb[(size_t)(2 * w + 1) * SS + cbase + 2 * l] = bv;
        }

        // ---- PV MMAs: warp w owns d-cols 8w..8w+7, accumulate unnormalized ----
#pragma unroll
        for (int k0 = 0; k0 < KC; k0 += 8) {
            float a0 = echunk[g * EC + k0 + tg];
            float a1 = echunk[(g + 8) * EC + k0 + tg];
            float a2 = echunk[g * EC + k0 + tg + 4];
            float a3 = echunk[(g + 8) * EC + k0 + tg + 4];
            float h0 = tf32r(a0), h1 = tf32r(a1), h2 = tf32r(a2), h3 = tf32r(a3);
            float lo0 = tf32r(a0 - h0), lo1 = tf32r(a1 - h1);
            float lo2 = tf32r(a2 - h2), lo3 = tf32r(a3 - h3);
            const float* ph = &VH[(8 * w + g) * VSTR + k0 + tg];
            const float* pl = &VL[(8 * w + g) * VSTR + k0 + tg];
            float bh0 = ph[0], bh1 = ph[4];
            float bl0 = pl[0], bl1 = pl[4];
            MMA8(oacc, h0, h1, h2, h3, bh0, bh1);
            MMA8(oacc, h0, h1, h2, h3, bl0, bl1);
            MMA8(oacc, lo0, lo1, lo2, lo3, bh0, bh1);
        }
    }

    // ===== row-sum reduction -> invs[16] + g_inv =====
    s0 += __shfl_xor_sync(0xffffffffu, s0, 1);
    s0 += __shfl_xor_sync(0xffffffffu, s0, 2);
    s1 += __shfl_xor_sync(0xffffffffu, s1, 1);
    s1 += __shfl_xor_sync(0xffffffffu, s1, 2);
    if (tg == 0) {
        part[g * 8 + w]       = s0;
        part[(g + 8) * 8 + w] = s1;
    }
    __syncthreads();
    if (tid < 16) {
        float t = 0.f;
#pragma unroll
        for (int j = 0; j < 8; j++) t += part[tid * 8 + j];
        float iv = 1.0f / t;
        invs[tid] = iv;
        g_inv[bh * SS + q0 + tid] = iv;
    }
    __syncthreads();

    // ===== write O (normalize here) =====
    const float invA = invs[g];
    const float invB = invs[g + 8];
    const int col = 8 * w + 2 * tg;
    *(float2*)&Ob[(size_t)g * DD + col] =
        make_float2(oacc[0] * invA, oacc[1] * invA);
    *(float2*)&Ob[(size_t)(g + 8) * DD + col] =
        make_float2(oacc[2] * invB, oacc[3] * invB);
}

// wts[row][k] *= g_inv[row]   (row = global row over NBH*SS)
__global__ __launch_bounds__(256, 8)
void norm_wts(float4* __restrict__ wts4) {
    size_t i = (size_t)blockIdx.x * 256 + threadIdx.x;  // float4 index
    float inv = g_inv[i >> 9];                          // 512 float4 per row
    float4 v = wts4[i];
    v.x *= inv; v.y *= inv; v.z *= inv; v.w *= inv;
    wts4[i] = v;
}

extern "C" void kernel_launch(void* const* d_in, const int* in_sizes, int n_in,
                              void* d_out, int out_size) {
    (void)in_sizes; (void)n_in; (void)out_size;
    const float* Q    = (const float*)d_in[0];
    const float* K    = (const float*)d_in[1];
    const float* V    = (const float*)d_in[2];
    const int*   mask = (const int*)d_in[3];
    float* out = (float*)d_out;
    float* wts = out + OUT_ELEMS;

    static int smem_set = 0;
    if (!smem_set) {
        cudaFuncSetAttribute(sdpa_fused,
                             cudaFuncAttributeMaxDynamicSharedMemorySize,
                             SMEM_BYTES);
        smem_set = 1;
    }

    dim3 grid(HH, SS / TQ, BB);  // h fastest -> mask tile reused across heads in L2
    sdpa_fused<<<grid, NT, SMEM_BYTES>>>(Q, K, V, mask, out, wts);

    const size_t n4 = (size_t)NBH * SS * SS / 4;
    norm_wts<<<(unsigned)(n4 / 256), 256>>>((float4*)wts);
}

// round 10
// speedup vs baseline: 4.1808x; 4.1808x over previous
#include <cuda_runtime.h>
#include <cuda_bf16.h>
#include <cuda_fp16.h>
#include <cstdint>

// Problem shape (fixed by reference)
#define BB 4
#define HH 16
#define SS 2048
#define DD 64
#define TQ 16            // queries per CTA
#define KC 128           // keys per chunk
#define NCHUNK (SS/KC)   // 16
#define NT 256
#define SCALE 0.125f

#define EPW 1028         // e-plane row stride, 32-bit words (1028 % 32 == 4)
#define KPS 136          // K plane row stride, words (136 % 32 == 8), rows = d2 (32)
#define VPS 68           // V plane row stride, words (68 % 32 == 4),  rows = d (64)

#define OUT_ELEMS (BB*HH*SS*DD)

#define W_EP 16448       // 16 * 1028
#define W_PL 4352        // max(32*136, 64*68) = 4352 (equal)
#define SMEM_WORDS (W_EP + 2*W_PL + TQ*DD + 128 + 16)
#define SMEM_BYTES (SMEM_WORDS * 4)

// D(16x8 f32) += A(16x16 bf16, row) * B(16x8 bf16, col)
#define MMA16(d, a0, a1, a2, a3, b0, b1)                                       \
    asm volatile(                                                              \
        "mma.sync.aligned.m16n8k16.row.col.f32.bf16.bf16.f32 "                 \
        "{%0,%1,%2,%3},{%4,%5,%6,%7},{%8,%9},{%0,%1,%2,%3};"                   \
        : "+f"(d[0]), "+f"(d[1]), "+f"(d[2]), "+f"(d[3])                       \
        : "r"(a0), "r"(a1), "r"(a2), "r"(a3), "r"(b0), "r"(b1))

// split (x,y) into packed bf16x2 hi and lo planes (hi + lo ~ fp32-16bit)
__device__ __forceinline__ void bsplit2(float x, float y, uint32_t& hi, uint32_t& lo) {
    __nv_bfloat162 H = __floats2bfloat162_rn(x, y);
    float2 hf = __bfloat1622float2(H);
    __nv_bfloat162 L = __floats2bfloat162_rn(x - hf.x, y - hf.y);
    hi = *reinterpret_cast<uint32_t*>(&H);
    lo = *reinterpret_cast<uint32_t*>(&L);
}

__device__ __forceinline__ uint32_t packh2(float x, float y) {
    __half2 v = __floats2half2_rn(x, y);
    return *reinterpret_cast<uint32_t*>(&v);
}

__global__ __launch_bounds__(NT, 2)
void sdpa_bf16(const float* __restrict__ Q, const float* __restrict__ K,
               const float* __restrict__ V, const int* __restrict__ mask,
               float* __restrict__ out, float* __restrict__ wts) {
    extern __shared__ uint32_t sm[];
    uint32_t* EP = sm;               // e-plane: 16 rows x 1028 words (fp16 pairs)
    uint32_t* PH = sm + W_EP;        // K/V hi plane (bf16 pairs)
    uint32_t* PL = PH + W_PL;        // K/V lo plane
    float* Qs   = (float*)(PL + W_PL);   // 16 x 64 raw Q
    float* part = Qs + TQ * DD;          // [16][8]
    float* invs = part + 128;            // [16]

    const int h  = blockIdx.x;
    const int q0 = blockIdx.y * TQ;
    const int b  = blockIdx.z;

    const int tid = threadIdx.x;
    const int w   = tid >> 5;   // warp 0..7
    const int l   = tid & 31;
    const int g   = l >> 2;     // 0..7
    const int tg  = l & 3;      // 0..3

    const size_t bh = (size_t)(b * HH + h);
    const float* Qb = Q + bh * SS * DD + (size_t)q0 * DD;
    const float* Kb = K + bh * SS * DD;
    const float* Vb = V + bh * SS * DD;
    const int*   Mb = mask + (size_t)b * SS * SS + (size_t)q0 * SS;
    float* Ob = out + bh * SS * DD + (size_t)q0 * DD;
    float* Wb = wts + bh * SS * SS + (size_t)q0 * SS;

    ((float4*)Qs)[tid] = ((const float4*)Qb)[tid];
    __syncthreads();

    // Q fragments: bf16 hi/lo split, SCALE folded. a0:(g,k),a1:(g+8,k),a2:(g,k+8),a3:(g+8,k+8)
    uint32_t Qh[4][4], Ql[4][4];
#pragma unroll
    for (int dk = 0; dk < 4; dk++) {
        const int base = 16 * dk + 2 * tg;
        float2 p00 = *(const float2*)&Qs[g * DD + base];
        float2 p10 = *(const float2*)&Qs[(g + 8) * DD + base];
        float2 p01 = *(const float2*)&Qs[g * DD + base + 8];
        float2 p11 = *(const float2*)&Qs[(g + 8) * DD + base + 8];
        bsplit2(p00.x * SCALE, p00.y * SCALE, Qh[dk][0], Ql[dk][0]);
        bsplit2(p10.x * SCALE, p10.y * SCALE, Qh[dk][1], Ql[dk][1]);
        bsplit2(p01.x * SCALE, p01.y * SCALE, Qh[dk][2], Ql[dk][2]);
        bsplit2(p11.x * SCALE, p11.y * SCALE, Qh[dk][3], Ql[dk][3]);
    }

    float s0 = 0.f, s1 = 0.f;   // row-sum partials for rows g, g+8

    // ================= Phase 1: e = exp(masked QK^T) into fp16 e-plane =====
    for (int c = 0; c < NCHUNK; c++) {
        const int cbase = c * KC;
        __syncthreads();
        // stage K chunk: lane = d2 (coalesced 256B rows), XOR-swizzled STS
#pragma unroll
        for (int j = 0; j < 16; j++) {
            const int key = 16 * w + j;
            float2 kv = *(const float2*)&Kb[(size_t)(cbase + key) * DD + 2 * l];
            uint32_t hi, lo;
            bsplit2(kv.x, kv.y, hi, lo);
            const int wi = l * KPS + (key ^ ((l >> 2) & 7));
            PH[wi] = hi;
            PL[wi] = lo;
        }
        __syncthreads();

        // mask for this warp's 16 keys (in flight during MMAs)
        const int mc = cbase + 16 * w + 2 * tg;
        int2 m00 = *(const int2*)&Mb[(size_t)g * SS + mc];
        int2 m01 = *(const int2*)&Mb[(size_t)g * SS + mc + 8];
        int2 m10 = *(const int2*)&Mb[(size_t)(g + 8) * SS + mc];
        int2 m11 = *(const int2*)&Mb[(size_t)(g + 8) * SS + mc + 8];

        float acc0[4] = {0.f, 0.f, 0.f, 0.f};
        float acc1[4] = {0.f, 0.f, 0.f, 0.f};
#pragma unroll
        for (int dk = 0; dk < 4; dk++) {
            const int d2a = 8 * dk + tg, d2b = d2a + 4;
            const int sa = (d2a >> 2) & 7, sb = (d2b >> 2) & 7;
#pragma unroll
            for (int jn = 0; jn < 2; jn++) {
                const int key = 16 * w + 8 * jn + g;
                const int ia = d2a * KPS + (key ^ sa);
                const int ib = d2b * KPS + (key ^ sb);
                uint32_t bh0 = PH[ia], bh1 = PH[ib];
                uint32_t bl0 = PL[ia], bl1 = PL[ib];
                float* A = jn ? acc1 : acc0;
                MMA16(A, Qh[dk][0], Qh[dk][1], Qh[dk][2], Qh[dk][3], bh0, bh1);
                MMA16(A, Qh[dk][0], Qh[dk][1], Qh[dk][2], Qh[dk][3], bl0, bl1);
                MMA16(A, Ql[dk][0], Ql[dk][1], Ql[dk][2], Ql[dk][3], bh0, bh1);
            }
        }
        // epilogue: mask -> exp -> fp16 pairs to e-plane, sums in regs
        {
            const int wc = c * 64 + 8 * w + tg;
            float e0 = m00.x ? __expf(acc0[0]) : 0.f;
            float e1 = m00.y ? __expf(acc0[1]) : 0.f;
            float e2 = m10.x ? __expf(acc0[2]) : 0.f;
            float e3 = m10.y ? __expf(acc0[3]) : 0.f;
            EP[g * EPW + wc]       = packh2(e0, e1);
            EP[(g + 8) * EPW + wc] = packh2(e2, e3);
            s0 += e0 + e1; s1 += e2 + e3;
            e0 = m01.x ? __expf(acc1[0]) : 0.f;
            e1 = m01.y ? __expf(acc1[1]) : 0.f;
            e2 = m11.x ? __expf(acc1[2]) : 0.f;
            e3 = m11.y ? __expf(acc1[3]) : 0.f;
            EP[g * EPW + wc + 4]       = packh2(e0, e1);
            EP[(g + 8) * EPW + wc + 4] = packh2(e2, e3);
            s0 += e0 + e1; s1 += e2 + e3;
        }
    }

    // ================= row-sum reduction -> invs[16] =======================
    s0 += __shfl_xor_sync(0xffffffffu, s0, 1);
    s0 += __shfl_xor_sync(0xffffffffu, s0, 2);
    s1 += __shfl_xor_sync(0xffffffffu, s1, 1);
    s1 += __shfl_xor_sync(0xffffffffu, s1, 2);
    if (tg == 0) {
        part[g * 8 + w]       = s0;
        part[(g + 8) * 8 + w] = s1;
    }
    __syncthreads();
    if (tid < 16) {
        float t = 0.f;
#pragma unroll
        for (int j = 0; j < 8; j++) t += part[tid * 8 + j];
        invs[tid] = 1.0f / t;
    }
    __syncthreads();

    // ================= Phase 2: normalized weights to global ===============
#pragma unroll
    for (int rr = 0; rr < 2; rr++) {
        const int r = 2 * w + rr;
        const float inv = invs[r];
        for (int j = 0; j < 16; j++) {
            uint2 u = *(const uint2*)&EP[r * EPW + 2 * (l + 32 * j)];
            float2 f0 = __half22float2(*reinterpret_cast<__half2*>(&u.x));
            float2 f1 = __half22float2(*reinterpret_cast<__half2*>(&u.y));
            float4 o = make_float4(f0.x * inv, f0.y * inv, f1.x * inv, f1.y * inv);
            *(float4*)&Wb[(size_t)r * SS + 4 * (l + 32 * j)] = o;
        }
    }

    // ================= Phase 3: O^T = V^T @ P^T ===========================
    const int dt = w & 3, nt = w >> 2;
    float oacc[4] = {0.f, 0.f, 0.f, 0.f};
    for (int c = 0; c < NCHUNK; c++) {
        const int cbase = c * KC;
        // stage V chunk: lane = d (coalesced 128B rows), pairs along keys
#pragma unroll
        for (int p = 0; p < 2; p++) {
            const int d = l + 32 * p;
            const int sw = (d >> 3) & 3;
#pragma unroll
            for (int j = 0; j < 8; j++) {
                const int k2 = 8 * w + j;
                float va = Vb[(size_t)(cbase + 2 * k2) * DD + d];
                float vb2 = Vb[(size_t)(cbase + 2 * k2 + 1) * DD + d];
                uint32_t hi, lo;
                bsplit2(va, vb2, hi, lo);
                const int wi = d * VPS + (k2 ^ sw);
                PH[wi] = hi;
                PL[wi] = lo;
            }
        }
        __syncthreads();
#pragma unroll
        for (int s = 0; s < 8; s++) {
            const int da = 16 * dt + g, db = da + 8;
            const int ca = 8 * s + tg, cb = ca + 4;
            const int sa2 = (da >> 3) & 3, sb2 = (db >> 3) & 3;
            const int i0 = da * VPS + (ca ^ sa2), i1 = db * VPS + (ca ^ sb2);
            const int i2 = da * VPS + (cb ^ sa2), i3 = db * VPS + (cb ^ sb2);
            uint32_t ah0 = PH[i0], ah1 = PH[i1], ah2 = PH[i2], ah3 = PH[i3];
            uint32_t al0 = PL[i0], al1 = PL[i1], al2 = PL[i2], al3 = PL[i3];
            const int bw = (8 * nt + g) * EPW + c * 64 + 8 * s + tg;
            uint32_t u0 = EP[bw], u1 = EP[bw + 4];
            uint32_t bh0, bl0, bh1, bl1;
            {
                float2 f = __half22float2(*reinterpret_cast<__half2*>(&u0));
                bsplit2(f.x, f.y, bh0, bl0);
            }
            {
                float2 f = __half22float2(*reinterpret_cast<__half2*>(&u1));
                bsplit2(f.x, f.y, bh1, bl1);
            }
            MMA16(oacc, ah0, ah1, ah2, ah3, bh0, bh1);
            MMA16(oacc, al0, al1, al2, al3, bh0, bh1);
            MMA16(oacc, ah0, ah1, ah2, ah3, bl0, bl1);
        }
        __syncthreads();
    }

    // write O (normalize with row inverses)
    const int row0 = 8 * nt + 2 * tg, row1 = row0 + 1;
    const int d0 = 16 * dt + g, d1 = d0 + 8;
    const float i0 = invs[row0], i1 = invs[row1];
    Ob[(size_t)row0 * DD + d0] = oacc[0] * i0;
    Ob[(size_t)row1 * DD + d0] = oacc[1] * i1;
    Ob[(size_t)row0 * DD + d1] = oacc[2] * i0;
    Ob[(size_t)row1 * DD + d1] = oacc[3] * i1;
}

extern "C" void kernel_launch(void* const* d_in, const int* in_sizes, int n_in,
                              void* d_out, int out_size) {
    (void)in_sizes; (void)n_in; (void)out_size;
    const float* Q    = (const float*)d_in[0];
    const float* K    = (const float*)d_in[1];
    const float* V    = (const float*)d_in[2];
    const int*   mask = (const int*)d_in[3];
    float* out = (float*)d_out;
    float* wts = out + OUT_ELEMS;

    static int smem_set = 0;
    if (!smem_set) {
        cudaFuncSetAttribute(sdpa_bf16,
                             cudaFuncAttributeMaxDynamicSharedMemorySize,
                             SMEM_BYTES);
        smem_set = 1;
    }

    dim3 grid(HH, SS / TQ, BB);  // h fastest -> mask tile reused across heads in L2
    sdpa_bf16<<<grid, NT, SMEM_BYTES>>>(Q, K, V, mask, out, wts);
}